// round 4
// baseline (speedup 1.0000x reference)
#include <cuda_runtime.h>

#define TILE 16
#define NBOX 64
#define TILES_PER_IMG 134   // 100 (L0 10x10) + 25 (L1 5x5) + 9 (L2 3x3)
#define MAX_B 64
#define NPART_MAX (TILES_PER_IMG * MAX_B)

// Per-block partial sums: [slot*3 + {0:cls,1:reg,2:npos}]
__device__ double g_partial[NPART_MAX * 3];

__global__ __launch_bounds__(256) void fcos_fused_kernel(
    const float* __restrict__ cls0, const float* __restrict__ cls1,
    const float* __restrict__ cls2,
    const float* __restrict__ reg0, const float* __restrict__ reg1,
    const float* __restrict__ reg2,
    const float* __restrict__ gt)
{
    __shared__ float s_gt[NBOX * 4];
    __shared__ float cx0[NBOX], cy0[NBOX], cx1[NBOX], cy1[NBOX], car[NBOX];
    __shared__ int s_ncand;
    __shared__ float s_red[3 * 8];

    const int bid = blockIdx.x;
    const int tid = threadIdx.x;
    const int b = bid / TILES_PER_IMG;
    int r = bid - b * TILES_PER_IMG;

    // Decode level + tile coords + per-level constants.
    const float* cls; const float* reg;
    int H, W, tx0, ty0;
    float stride, low, high;
    if (r < 100) {
        cls = cls0; reg = reg0; H = 160; W = 160;
        stride = 4.f; low = -1.f; high = 64.f;
        ty0 = r / 10; tx0 = r - ty0 * 10;
    } else if (r < 125) {
        r -= 100;
        cls = cls1; reg = reg1; H = 80; W = 80;
        stride = 8.f; low = 64.f; high = 128.f;
        ty0 = r / 5; tx0 = r - ty0 * 5;
    } else {
        r -= 125;
        cls = cls2; reg = reg2; H = 40; W = 40;
        stride = 16.f; low = 128.f; high = 99999.f;
        ty0 = r / 3; tx0 = r - ty0 * 3;
    }

    // Load this image's 64 boxes (256 floats) coalesced.
    s_gt[tid] = gt[b * NBOX * 4 + tid];
    __syncthreads();

    const int w0 = tx0 * TILE;
    const int h0 = ty0 * TILE;
    const float x_min = (w0 + 0.5f) * stride;
    const float x_max = (min(w0 + TILE - 1, W - 1) + 0.5f) * stride;
    const float y_min = (h0 + 0.5f) * stride;
    const float y_max = (min(h0 + TILE - 1, H - 1) + 0.5f) * stride;

    // Warp 0: ordered compaction of candidate boxes for this tile.
    // For a point strictly inside a box: l+r = bw, t+b = bh, hence
    //   max(w,h)/2 <= max(l,t,r,b) < max(w,h).
    // So in_lvl requires mwh > low and mwh/2 < high; in_box requires
    // tile-bbox overlap. These are necessary conditions => superset kept.
    if (tid < 32) {
        int base = 0;
        #pragma unroll
        for (int chunk = 0; chunk < 2; ++chunk) {
            const int m = tid + chunk * 32;
            const float bx0 = s_gt[m * 4 + 0];
            const float by0 = s_gt[m * 4 + 1];
            const float bx1 = s_gt[m * 4 + 2];
            const float by1 = s_gt[m * 4 + 3];
            const float bw = bx1 - bx0, bh = by1 - by0;
            const float mwh = fmaxf(bw, bh);
            const bool keep = (bx0 < x_max) && (bx1 > x_min) &&
                              (by0 < y_max) && (by1 > y_min) &&
                              (mwh > low) && (0.5f * mwh < high);
            const unsigned mask = __ballot_sync(0xffffffffu, keep);
            if (keep) {
                const int pos = base + __popc(mask & ((1u << tid) - 1u));
                cx0[pos] = bx0; cy0[pos] = by0;
                cx1[pos] = bx1; cy1[pos] = by1;
                car[pos] = bw * bh;
            }
            base += __popc(mask);
        }
        if (tid == 0) s_ncand = base;
    }
    __syncthreads();

    const int tx = tid & (TILE - 1);
    const int ty = tid >> 4;
    const int w = w0 + tx;
    const int h = h0 + ty;

    float cls_c = 0.f, reg_c = 0.f, np_c = 0.f;

    if (w < W && h < H) {
        const float x = (w + 0.5f) * stride;
        const float y = (h + 0.5f) * stride;
        const int nc = s_ncand;

        float best = __int_as_float(0x7f800000);  // +inf
        int bslot = -1;
        // Candidates preserve original box-index order; strict < keeps the
        // first minimum, matching jnp.argmin tie-breaking.
        for (int c = 0; c < nc; ++c) {
            const float l = x - cx0[c];
            const float t = y - cy0[c];
            const float rr = cx1[c] - x;
            const float bo = cy1[c] - y;
            const float mn = fminf(fminf(l, t), fminf(rr, bo));
            const float mx = fmaxf(fmaxf(l, t), fmaxf(rr, bo));
            const bool ok = (mn > 0.f) & (mx > low) & (mx < high);
            const float a = car[c];
            if (ok && a < best) { best = a; bslot = c; }
        }

        const int HW = H * W;
        const int pidx = h * W + w;
        const float z = cls[(size_t)b * HW + pidx];
        const float* rb = reg + (size_t)b * 4 * HW + pidx;
        const float pl = rb[0];
        const float pt = rb[HW];
        const float pr = rb[2 * HW];
        const float pb = rb[3 * HW];

        float gt_iou = 0.f;
        if (bslot >= 0) {
            const float tl = x - cx0[bslot];
            const float tt = y - cy0[bslot];
            const float tr = cx1[bslot] - x;
            const float tb = cy1[bslot] - y;
            const float w_i = fminf(pl, tl) + fminf(pr, tr);
            const float h_i = fminf(pt, tt) + fminf(pb, tb);
            const float a_i = fmaxf(w_i, 0.f) * fmaxf(h_i, 0.f);
            const float a_p = (pl + pr) * (pt + pb);
            const float a_t = (tl + tr) * (tt + tb);
            const float a_u = a_p + a_t - a_i + 1e-7f;
            const float iou = a_i / a_u;
            gt_iou = fminf(fmaxf(iou, 0.f), 1.f);
            const float w_e = fmaxf(pl, tl) + fmaxf(pr, tr);
            const float h_e = fmaxf(pt, tt) + fmaxf(pb, tb);
            const float a_e = fmaxf(w_e, 0.f) * fmaxf(h_e, 0.f) + 1e-7f;
            const float giou = iou - (a_e - a_u) / a_e;
            reg_c = 1.f - giou;
            np_c = 1.f;
        }

        // Varifocal loss (branchless stable log-sigmoid):
        //   log_p  = min(z,0)  - log1p(exp(-|z|))
        //   log_np = min(-z,0) - log1p(exp(-|z|))
        const float az = fabsf(z);
        const float e = expf(-az);
        const float l1 = log1pf(e);
        const float log_p  = fminf(z, 0.f) - l1;
        const float log_np = fminf(-z, 0.f) - l1;
        const float p = (z >= 0.f ? 1.f : e) / (1.f + e);
        if (gt_iou > 0.f)
            cls_c = -gt_iou * (gt_iou * log_p + (1.f - gt_iou) * log_np);
        else
            cls_c = -0.75f * p * p * log_np;
    }

    // Block reduction: warp shuffle -> shared -> thread 0 writes partial slot.
    const unsigned fm = 0xffffffffu;
    #pragma unroll
    for (int o = 16; o > 0; o >>= 1) {
        cls_c += __shfl_down_sync(fm, cls_c, o);
        reg_c += __shfl_down_sync(fm, reg_c, o);
        np_c  += __shfl_down_sync(fm, np_c, o);
    }
    const int lane = tid & 31;
    const int wid = tid >> 5;
    if (lane == 0) {
        s_red[wid]      = cls_c;
        s_red[8 + wid]  = reg_c;
        s_red[16 + wid] = np_c;
    }
    __syncthreads();
    if (tid == 0) {
        float a = 0.f, bb = 0.f, cc = 0.f;
        #pragma unroll
        for (int i = 0; i < 8; ++i) {
            a  += s_red[i];
            bb += s_red[8 + i];
            cc += s_red[16 + i];
        }
        g_partial[bid * 3 + 0] = (double)a;
        g_partial[bid * 3 + 1] = (double)bb;
        g_partial[bid * 3 + 2] = (double)cc;
    }
}

__global__ __launch_bounds__(256) void finalize_kernel(float* out, int B, int nblocks) {
    __shared__ double s0[256], s1[256], s2[256];
    const int tid = threadIdx.x;
    double a = 0.0, b = 0.0, c = 0.0;
    for (int i = tid; i < nblocks; i += 256) {
        a += g_partial[i * 3 + 0];
        b += g_partial[i * 3 + 1];
        c += g_partial[i * 3 + 2];
    }
    s0[tid] = a; s1[tid] = b; s2[tid] = c;
    __syncthreads();
    for (int o = 128; o > 0; o >>= 1) {
        if (tid < o) {
            s0[tid] += s0[tid + o];
            s1[tid] += s1[tid + o];
            s2[tid] += s2[tid + o];
        }
        __syncthreads();
    }
    if (tid == 0) {
        const double cls = s0[0], reg = s1[0], np = s2[0];
        const double navg = fmax(1.0, np / (double)B);
        out[0] = (float)((cls + reg) / navg);
        out[1] = (float)(cls / navg);
        out[2] = (float)(reg / navg);
    }
}

extern "C" void kernel_launch(void* const* d_in, const int* in_sizes, int n_in,
                              void* d_out, int out_size) {
    const float* cls0 = (const float*)d_in[0];  // (B,1,160,160)
    const float* cls1 = (const float*)d_in[1];  // (B,1,80,80)
    const float* cls2 = (const float*)d_in[2];  // (B,1,40,40)
    const float* reg0 = (const float*)d_in[3];  // (B,4,160,160)
    const float* reg1 = (const float*)d_in[4];  // (B,4,80,80)
    const float* reg2 = (const float*)d_in[5];  // (B,4,40,40)
    const float* gt   = (const float*)d_in[6];  // (B,64,4)
    float* out = (float*)d_out;

    int B = in_sizes[6] / (NBOX * 4);
    if (B > MAX_B) B = MAX_B;
    const int nblocks = B * TILES_PER_IMG;

    fcos_fused_kernel<<<nblocks, 256>>>(cls0, cls1, cls2, reg0, reg1, reg2, gt);
    finalize_kernel<<<1, 256>>>(out, B, nblocks);
}